// round 14
// baseline (speedup 1.0000x reference)
#include <cuda_runtime.h>
#include <cuda_bf16.h>
#include <math.h>
#include <stdint.h>

#define T_ 16
#define B_ 1024
#define F_ 512
#define H_ 128
#define L_ 512
#define C_ 100
#define CP_ 128   // classes padded to 128 for the tensor GEMM

// ---------------- scratch (static device globals; zero-initialized) ---------
__device__ __nv_bfloat16 g_featb[B_ * F_];        // 1 MB
__device__ __nv_bfloat16 g_w1t[T_ * H_ * F_];     // 2 MB  (W1^T per tree: [H][F])
__device__ __nv_bfloat16 g_w2t[T_ * L_ * H_];     // 2 MB  (W2^T per tree: [L][H])
__device__ __nv_bfloat16 g_hb[T_ * B_ * H_];      // 4 MB
__device__ __nv_bfloat16 g_pb[T_ * B_ * L_];      // 16 MB (bf16 sigmoid output)
__device__ __nv_bfloat16 g_mub[T_ * B_ * L_];     // 16 MB
__device__ __nv_bfloat16 g_lpT[T_ * CP_ * L_];    // 2 MB (rows >= C_ stay 0 forever)
__device__ float         g_part[T_ * B_ * C_];    // 6.6 MB

__device__ __forceinline__ float sigmoidf(float x) {
    return 1.0f / (1.0f + __expf(-x));
}

__device__ __forceinline__ uint32_t smem_u32(const void* p) {
    uint32_t a;
    asm("{ .reg .u64 t; cvta.to.shared.u64 t, %1; cvt.u32.u64 %0, t; }"
        : "=r"(a) : "l"(p));
    return a;
}

// swizzled byte offset inside a [128 rows x 128 bytes] smem tile
__device__ __forceinline__ uint32_t swz(int row, int colBytes) {
    return (uint32_t)(row * 128 + (colBytes ^ ((row & 7) << 4)));
}

__device__ __forceinline__ void cp_async16(uint32_t dst, const void* src) {
    asm volatile("cp.async.cg.shared.global [%0], [%1], 16;"
        :: "r"(dst), "l"(src) : "memory");
}
#define CP_ASYNC_COMMIT() asm volatile("cp.async.commit_group;" ::: "memory")
#define CP_ASYNC_WAIT_1() asm volatile("cp.async.wait_group 1;" ::: "memory")
#define CP_ASYNC_WAIT_0() asm volatile("cp.async.wait_group 0;" ::: "memory")

__device__ __forceinline__ void ldsm_x4(uint32_t& r0, uint32_t& r1,
                                        uint32_t& r2, uint32_t& r3, uint32_t addr) {
    asm volatile("ldmatrix.sync.aligned.m8n8.x4.shared.b16 {%0,%1,%2,%3}, [%4];"
        : "=r"(r0), "=r"(r1), "=r"(r2), "=r"(r3) : "r"(addr) : "memory");
}

__device__ __forceinline__ void mma16816(float* c, const uint32_t* a, const uint32_t* b) {
    asm volatile(
        "mma.sync.aligned.m16n8k16.row.col.f32.bf16.bf16.f32 "
        "{%0,%1,%2,%3}, {%4,%5,%6,%7}, {%8,%9}, {%0,%1,%2,%3};"
        : "+f"(c[0]), "+f"(c[1]), "+f"(c[2]), "+f"(c[3])
        : "r"(a[0]), "r"(a[1]), "r"(a[2]), "r"(a[3]), "r"(b[0]), "r"(b[1]));
}

// ===========================================================================
// HMMA batched GEMM, 2-stage cp.async pipeline, dynamic smem (4 x 16KB bufs).
// D[128 x 128] = A[128,K] @ Bw[128,K]^T  (bf16, f32 acc)
// A: [t][M][K] bf16 row-major.  Bw: [t][N][K] bf16 row-major (i.e. B^T).
// mode 0: out = bf16( relu(D + bias) )      (GEMM1 -> g_hb)
// mode 1: out = bf16( sigmoid(D + bias) )   (GEMM2 -> g_pb)
// mode 2: out = f32 ( D ), cols < C_ only   (final -> g_part, row stride C_)
// ===========================================================================
__global__ __launch_bounds__(256) void gemm_tc(
    const __nv_bfloat16* __restrict__ A, long strideAt,
    const __nv_bfloat16* __restrict__ Bw, long strideBt,
    const float* __restrict__ bias, long strideBiasT,
    void* __restrict__ Cout, long strideCt,
    int K, int Nfull, int mode)
{
    extern __shared__ __align__(128) uint8_t dynS[];
    // layout: A0 @0, A1 @16K, B0 @32K, B1 @48K
    __shared__ float sBias[128];

    int tid = threadIdx.x;
    int wid = tid >> 5;
    int lane = tid & 31;
    int t = blockIdx.z;
    int m0 = blockIdx.x * 128;
    int n0 = blockIdx.y * 128;

    const __nv_bfloat16* Ap = A + (long)t * strideAt + (long)m0 * K;
    const __nv_bfloat16* Bp = Bw + (long)t * strideBt + (long)n0 * K;

    if (tid < 128)
        sBias[tid] = (mode < 2) ? bias[(long)t * strideBiasT + n0 + tid] : 0.0f;

    int wm0 = (wid & 1) * 64;    // warp m-origin within tile
    int wn0 = (wid >> 1) * 32;   // warp n-origin within tile

    uint32_t base = smem_u32(dynS);
    uint32_t bufA[2] = { base, base + 16384 };
    uint32_t bufB[2] = { base + 32768, base + 49152 };

    // ldmatrix lane geometry (byte offsets relative to tile base)
    int aRow = wm0 + (lane & 15);
    int aK   = (lane >> 4) * 16;                     // byte offset of k-half
    uint32_t aRel = (uint32_t)aRow * 128;
    uint32_t aXor = (aRow & 7) << 4;

    int bRow = wn0 + (lane & 7) + ((lane >> 4) & 1) * 8;
    int bK   = ((lane >> 3) & 1) * 16;
    uint32_t bRel = (uint32_t)bRow * 128;
    uint32_t bXor = (bRow & 7) << 4;

    // per-thread cp.async geometry: 2 threads per row, each covers 4x16B/tile
    int ldRow = tid >> 1;                 // 0..127
    int ldCb  = (tid & 1) * 16;           // byte col of first 16B granule

    float acc[4][4][4];
    #pragma unroll
    for (int mt = 0; mt < 4; mt++)
        #pragma unroll
        for (int nt = 0; nt < 4; nt++)
            #pragma unroll
            for (int e = 0; e < 4; e++) acc[mt][nt][e] = 0.0f;

    int nch = K >> 6;                                // K-chunks of 64

    // fill chunk ch into buffer ch&1 (full coverage: 4 granules/thread/tile)
    auto fill = [&](int ch) {
        int k0 = ch << 6;
        uint32_t bA = bufA[ch & 1], bB = bufB[ch & 1];
        #pragma unroll
        for (int l = 0; l < 4; l++) {
            int cb = ldCb + l * 32;
            uint32_t off = swz(ldRow, cb);
            cp_async16(bA + off, Ap + (long)ldRow * K + k0 + (cb >> 1));
            cp_async16(bB + off, Bp + (long)ldRow * K + k0 + (cb >> 1));
        }
        CP_ASYNC_COMMIT();
    };

    fill(0);
    for (int ch = 0; ch < nch; ch++) {
        if (ch + 1 < nch) { fill(ch + 1); CP_ASYNC_WAIT_1(); }
        else             { CP_ASYNC_WAIT_0(); }
        __syncthreads();

        uint32_t bA = bufA[ch & 1], bB = bufB[ch & 1];
        #pragma unroll
        for (int kk = 0; kk < 4; kk++) {             // 4 x k16 steps
            int kb = kk * 32;                        // byte offset of k16
            uint32_t aF[4][4], bF[2][4];
            #pragma unroll
            for (int mt = 0; mt < 4; mt++)
                ldsm_x4(aF[mt][0], aF[mt][1], aF[mt][2], aF[mt][3],
                        bA + aRel + mt * (16 * 128) + ((kb + aK) ^ aXor));
            #pragma unroll
            for (int ntp = 0; ntp < 2; ntp++)
                ldsm_x4(bF[ntp][0], bF[ntp][1], bF[ntp][2], bF[ntp][3],
                        bB + bRel + ntp * (16 * 128) + ((kb + bK) ^ bXor));
            #pragma unroll
            for (int mt = 0; mt < 4; mt++)
                #pragma unroll
                for (int nt = 0; nt < 4; nt++)
                    mma16816(acc[mt][nt], aF[mt], &bF[nt >> 1][(nt & 1) * 2]);
        }
        __syncthreads();
    }

    // ---------------- epilogue (fragment layout: c0,c1 row r, c2,c3 row r+8) --
    int rIn = lane >> 2;           // 0..7
    int cIn = (lane & 3) * 2;      // 0,2,4,6
    #pragma unroll
    for (int mt = 0; mt < 4; mt++) {
        long rowLo = m0 + wm0 + mt * 16 + rIn;
        long rowHi = rowLo + 8;
        #pragma unroll
        for (int nt = 0; nt < 4; nt++) {
            int col = wn0 + nt * 8 + cIn;            // 0..127 within tile
            float b0 = sBias[col], b1 = sBias[col + 1];
            float v0 = acc[mt][nt][0] + b0, v1 = acc[mt][nt][1] + b1;
            float v2 = acc[mt][nt][2] + b0, v3 = acc[mt][nt][3] + b1;
            if (mode == 0) {
                __nv_bfloat16* o = (__nv_bfloat16*)Cout + (long)t * strideCt;
                *(__nv_bfloat162*)(o + rowLo * Nfull + n0 + col) =
                    __floats2bfloat162_rn(fmaxf(v0, 0.f), fmaxf(v1, 0.f));
                *(__nv_bfloat162*)(o + rowHi * Nfull + n0 + col) =
                    __floats2bfloat162_rn(fmaxf(v2, 0.f), fmaxf(v3, 0.f));
            } else if (mode == 1) {
                __nv_bfloat16* o = (__nv_bfloat16*)Cout + (long)t * strideCt;
                *(__nv_bfloat162*)(o + rowLo * Nfull + n0 + col) =
                    __floats2bfloat162_rn(sigmoidf(v0), sigmoidf(v1));
                *(__nv_bfloat162*)(o + rowHi * Nfull + n0 + col) =
                    __floats2bfloat162_rn(sigmoidf(v2), sigmoidf(v3));
            } else {
                if (col < C_) {
                    float* o = (float*)Cout + (long)t * strideCt;
                    *(float2*)(o + rowLo * C_ + col) = make_float2(v0, v1);
                    *(float2*)(o + rowHi * C_ + col) = make_float2(v2, v3);
                }
            }
        }
    }
}

// ---------------------------------------------------------------------------
// elementwise fp32 -> bf16
// ---------------------------------------------------------------------------
__global__ __launch_bounds__(256) void conv_bf16(const float* __restrict__ in,
                                                 __nv_bfloat16* __restrict__ out,
                                                 int n)
{
    int i = blockIdx.x * 256 + threadIdx.x;
    if (i < n) out[i] = __float2bfloat16(in[i]);
}

// ---------------------------------------------------------------------------
// batched transpose + convert: in[t][R][Cc] f32  ->  out[t][Cc][R] bf16
// ---------------------------------------------------------------------------
__global__ __launch_bounds__(256) void transpose_bf16(const float* __restrict__ in,
                                                      __nv_bfloat16* __restrict__ out,
                                                      int R, int Cc)
{
    __shared__ float tile[32][33];
    int t = blockIdx.z;
    in  += (long)t * R * Cc;
    out += (long)t * R * Cc;
    int x = blockIdx.x * 32 + threadIdx.x;
    int y0 = blockIdx.y * 32;
    #pragma unroll
    for (int j = threadIdx.y; j < 32; j += 8)
        tile[j][threadIdx.x] = in[(long)(y0 + j) * Cc + x];
    __syncthreads();
    int xo = y0 + threadIdx.x;
    int yo0 = blockIdx.x * 32;
    #pragma unroll
    for (int j = threadIdx.y; j < 32; j += 8)
        out[(long)(yo0 + j) * R + xo] = __float2bfloat16(tile[threadIdx.x][j]);
}

// ---------------------------------------------------------------------------
// Routing product: 4 batch-rows per block (contiguous load), bf16 in/out.
// grid = (B_/4, T_), block = 512.
// ---------------------------------------------------------------------------
__global__ __launch_bounds__(512) void mu_kernel(const __nv_bfloat16* __restrict__ p,
                                                 __nv_bfloat16* __restrict__ mub)
{
    __shared__ float ps[4][L_];

    int b0 = blockIdx.x * 4;
    int t  = blockIdx.y;
    int tid = threadIdx.x;

    long base = ((long)t * B_ + b0) * L_;
    // 4 rows x 512 bf16 = 2048 contiguous bf16 = 1024 bf16x2
    const __nv_bfloat162* src = (const __nv_bfloat162*)(p + base);
    #pragma unroll
    for (int i = tid; i < 1024; i += 512) {
        __nv_bfloat162 v = src[i];
        int r = i >> 8;
        int c = (i & 255) * 2;
        ps[r][c]     = __bfloat162float(__low2bfloat16(v));
        ps[r][c + 1] = __bfloat162float(__high2bfloat16(v));
    }
    __syncthreads();

    int l = tid;
    #pragma unroll
    for (int r = 0; r < 4; r++) {
        float m = 1.0f;
        #pragma unroll
        for (int d = 0; d <= 8; d++) {
            int node = (1 << d) - 1 + (l >> (9 - d));
            float v = ps[r][node];
            m *= ((l >> (8 - d)) & 1) ? (1.0f - v) : v;
        }
        mub[base + (long)r * L_ + l] = __float2bfloat16(m);
    }
}

// ---------------------------------------------------------------------------
// softmax over classes with smem-staged transpose.
// grid = (L_/32, T_), block = 256 (8 warps x 4 rows). Coalesced 64B row writes.
// ---------------------------------------------------------------------------
__global__ __launch_bounds__(256) void softmaxT_kernel(const float* __restrict__ pi,
                                                       __nv_bfloat16* __restrict__ lpT)
{
    __shared__ __nv_bfloat16 tile[C_][34];

    int l0 = blockIdx.x * 32;
    int t  = blockIdx.y;
    int wid = threadIdx.x >> 5;
    int lane = threadIdx.x & 31;

    #pragma unroll
    for (int r = 0; r < 4; r++) {
        int lloc = wid * 4 + r;                        // 0..31
        const float* x = pi + ((long)t * L_ + l0 + lloc) * C_;

        float v[4];
        float mx = -1e30f;
        #pragma unroll
        for (int i = 0; i < 4; i++) {
            int c = lane + i * 32;
            v[i] = (c < C_) ? x[c] : -1e30f;
            mx = fmaxf(mx, v[i]);
        }
        #pragma unroll
        for (int o = 16; o > 0; o >>= 1)
            mx = fmaxf(mx, __shfl_xor_sync(0xffffffffu, mx, o));

        float s = 0.0f;
        #pragma unroll
        for (int i = 0; i < 4; i++) {
            int c = lane + i * 32;
            v[i] = (c < C_) ? expf(v[i] - mx) : 0.0f;
            s += v[i];
        }
        #pragma unroll
        for (int o = 16; o > 0; o >>= 1)
            s += __shfl_xor_sync(0xffffffffu, s, o);

        float inv = 1.0f / s;
        #pragma unroll
        for (int i = 0; i < 4; i++) {
            int c = lane + i * 32;
            if (c < C_) tile[c][lloc] = __float2bfloat16(v[i] * inv);
        }
    }
    __syncthreads();

    // coalesced write-out: rows of 32 contiguous bf16 (64B)
    __nv_bfloat16* o = lpT + (long)t * CP_ * L_ + l0;
    for (int idx = threadIdx.x; idx < C_ * 32; idx += 256) {
        int c = idx >> 5;
        int l = idx & 31;
        o[(long)c * L_ + l] = tile[c][l];
    }
}

// ---------------------------------------------------------------------------
// Deterministic reduce over trees + scale + log
// ---------------------------------------------------------------------------
__global__ __launch_bounds__(256) void finalize_kernel(const float* __restrict__ part,
                                                       float* __restrict__ out)
{
    int i = blockIdx.x * 256 + threadIdx.x;
    if (i >= B_ * C_) return;
    float s = 0.0f;
    #pragma unroll
    for (int t = 0; t < T_; t++) s += part[(long)t * B_ * C_ + i];
    out[i] = logf(s * (1.0f / (float)(L_ * T_)));
}

// ---------------------------------------------------------------------------
extern "C" void kernel_launch(void* const* d_in, const int* in_sizes, int n_in,
                              void* d_out, int out_size)
{
    const float* feat = (const float*)d_in[0];   // [B, F]
    const float* W1   = (const float*)d_in[1];   // [T, F, H]
    const float* b1   = (const float*)d_in[2];   // [T, H]
    const float* W2   = (const float*)d_in[3];   // [T, H, L]
    const float* b2   = (const float*)d_in[4];   // [T, L]
    const float* pi   = (const float*)d_in[5];   // [T, L, C]
    float* out        = (float*)d_out;           // [B, C]

    void *pfb, *pw1t, *pw2t, *phb, *ppb, *pmub, *plpT, *ppart;
    cudaGetSymbolAddress(&pfb,   g_featb);
    cudaGetSymbolAddress(&pw1t,  g_w1t);
    cudaGetSymbolAddress(&pw2t,  g_w2t);
    cudaGetSymbolAddress(&phb,   g_hb);
    cudaGetSymbolAddress(&ppb,   g_pb);
    cudaGetSymbolAddress(&pmub,  g_mub);
    cudaGetSymbolAddress(&plpT,  g_lpT);
    cudaGetSymbolAddress(&ppart, g_part);

    static int smem_set = 0;
    if (!smem_set) {
        cudaFuncSetAttribute(gemm_tc,
            cudaFuncAttributeMaxDynamicSharedMemorySize, 65536);
        smem_set = 1;
    }
    const int GSM = 65536;

    // operand prep
    conv_bf16<<<(B_ * F_ + 255) / 256, 256>>>(feat, (__nv_bfloat16*)pfb, B_ * F_);
    transpose_bf16<<<dim3(H_ / 32, F_ / 32, T_), dim3(32, 8)>>>(
        W1, (__nv_bfloat16*)pw1t, F_, H_);
    transpose_bf16<<<dim3(L_ / 32, H_ / 32, T_), dim3(32, 8)>>>(
        W2, (__nv_bfloat16*)pw2t, H_, L_);
    softmaxT_kernel<<<dim3(L_ / 32, T_), 256>>>(pi, (__nv_bfloat16*)plpT);

    // GEMM1: h = relu(feat @ W1 + b1)  M=1024 N=128 K=512
    gemm_tc<<<dim3(8, 1, T_), 256, GSM>>>(
        (const __nv_bfloat16*)pfb, 0L,
        (const __nv_bfloat16*)pw1t, (long)H_ * F_,
        b1, (long)H_,
        phb, (long)B_ * H_,
        F_, H_, /*mode=*/0);

    // GEMM2: p = sigmoid(h @ W2 + b2)  M=1024 N=512 K=128  (bf16 out)
    gemm_tc<<<dim3(8, 4, T_), 256, GSM>>>(
        (const __nv_bfloat16*)phb, (long)B_ * H_,
        (const __nv_bfloat16*)pw2t, (long)L_ * H_,
        b2, (long)L_,
        ppb, (long)B_ * L_,
        H_, L_, /*mode=*/1);

    // routing products (bf16 in, bf16 out)
    mu_kernel<<<dim3(B_ / 4, T_), 512>>>((const __nv_bfloat16*)ppb,
                                         (__nv_bfloat16*)pmub);

    // final contraction per tree: part[t] = mu[t] @ leafpT[t]^T
    gemm_tc<<<dim3(8, 1, T_), 256, GSM>>>(
        (const __nv_bfloat16*)pmub, (long)B_ * L_,
        (const __nv_bfloat16*)plpT, (long)CP_ * L_,
        b1 /*unused in mode 2*/, 0L,
        ppart, (long)B_ * C_,
        L_, 0, /*mode=*/2);

    // sum over trees, scale, log
    finalize_kernel<<<(B_ * C_ + 255) / 256, 256>>>((const float*)ppart, out);
}

// round 15
// speedup vs baseline: 1.2914x; 1.2914x over previous
#include <cuda_runtime.h>
#include <cuda_bf16.h>
#include <math.h>
#include <stdint.h>

#define T_ 16
#define B_ 1024
#define F_ 512
#define H_ 128
#define L_ 512
#define C_ 100
#define CP_ 128   // classes padded to 128 for the tensor GEMM

// ---------------- scratch (static device globals; zero-initialized) ---------
__device__ __nv_bfloat16 g_featb[B_ * F_];        // 1 MB
__device__ __nv_bfloat16 g_w1t[T_ * H_ * F_];     // 2 MB  (W1^T per tree: [H][F])
__device__ __nv_bfloat16 g_w2t[T_ * L_ * H_];     // 2 MB  (W2^T per tree: [L][H])
__device__ __nv_bfloat16 g_hb[T_ * B_ * H_];      // 4 MB
__device__ __nv_bfloat16 g_pb[T_ * B_ * L_];      // 16 MB (bf16 sigmoid output)
__device__ __nv_bfloat16 g_mub[T_ * B_ * L_];     // 16 MB
__device__ __nv_bfloat16 g_lpT[T_ * CP_ * L_];    // 2 MB (rows >= C_ stay 0 forever)
__device__ float         g_part[T_ * B_ * C_];    // 6.6 MB

__device__ __forceinline__ float sigmoidf(float x) {
    return 1.0f / (1.0f + __expf(-x));
}

__device__ __forceinline__ uint32_t smem_u32(const void* p) {
    uint32_t a;
    asm("{ .reg .u64 t; cvta.to.shared.u64 t, %1; cvt.u32.u64 %0, t; }"
        : "=r"(a) : "l"(p));
    return a;
}

// swizzled byte offset inside a [128 rows x 128 bytes] smem tile
__device__ __forceinline__ uint32_t swz(int row, int colBytes) {
    return (uint32_t)(row * 128 + (colBytes ^ ((row & 7) << 4)));
}

__device__ __forceinline__ void cp_async16(uint32_t dst, const void* src) {
    asm volatile("cp.async.cg.shared.global [%0], [%1], 16;"
        :: "r"(dst), "l"(src) : "memory");
}
#define CP_ASYNC_WAIT_ALL() \
    asm volatile("cp.async.wait_all;" ::: "memory")

__device__ __forceinline__ void ldsm_x4(uint32_t& r0, uint32_t& r1,
                                        uint32_t& r2, uint32_t& r3, uint32_t addr) {
    asm volatile("ldmatrix.sync.aligned.m8n8.x4.shared.b16 {%0,%1,%2,%3}, [%4];"
        : "=r"(r0), "=r"(r1), "=r"(r2), "=r"(r3) : "r"(addr) : "memory");
}

__device__ __forceinline__ void mma16816(float* c, const uint32_t* a, const uint32_t* b) {
    asm volatile(
        "mma.sync.aligned.m16n8k16.row.col.f32.bf16.bf16.f32 "
        "{%0,%1,%2,%3}, {%4,%5,%6,%7}, {%8,%9}, {%0,%1,%2,%3};"
        : "+f"(c[0]), "+f"(c[1]), "+f"(c[2]), "+f"(c[3])
        : "r"(a[0]), "r"(a[1]), "r"(a[2]), "r"(a[3]), "r"(b[0]), "r"(b[1]));
}

// ===========================================================================
// HMMA batched GEMM (single-buffer, static smem — the proven 92.9us version)
// D[128 x 128] = A[128,K] @ Bw[128,K]^T  (bf16, f32 acc)
// A: [t][M][K] bf16 row-major.  Bw: [t][N][K] bf16 row-major (i.e. B^T).
// mode 0: out = bf16( relu(D + bias) )      (GEMM1 -> g_hb)
// mode 1: out = bf16( sigmoid(D + bias) )   (GEMM2 -> g_pb)
// mode 2: out = f32 ( D ), cols < C_ only   (final -> g_part, row stride C_)
// ===========================================================================
__global__ __launch_bounds__(256) void gemm_tc(
    const __nv_bfloat16* __restrict__ A, long strideAt,
    const __nv_bfloat16* __restrict__ Bw, long strideBt,
    const float* __restrict__ bias, long strideBiasT,
    void* __restrict__ Cout, long strideCt,
    int K, int Nfull, int mode)
{
    __shared__ __align__(128) uint8_t smA[128 * 128];   // 128 rows x 64 bf16
    __shared__ __align__(128) uint8_t smB[128 * 128];
    __shared__ float sBias[128];

    int tid = threadIdx.x;
    int wid = tid >> 5;
    int lane = tid & 31;
    int t = blockIdx.z;
    int m0 = blockIdx.x * 128;
    int n0 = blockIdx.y * 128;

    const __nv_bfloat16* Ap = A + (long)t * strideAt + (long)m0 * K;
    const __nv_bfloat16* Bp = Bw + (long)t * strideBt + (long)n0 * K;

    if (tid < 128)
        sBias[tid] = (mode < 2) ? bias[(long)t * strideBiasT + n0 + tid] : 0.0f;

    int wm0 = (wid & 1) * 64;    // warp m-origin within tile
    int wn0 = (wid >> 1) * 32;   // warp n-origin within tile

    uint32_t baseA = smem_u32(smA);
    uint32_t baseB = smem_u32(smB);

    // ldmatrix lane geometry (byte addresses into the swizzled tiles)
    int aRow = wm0 + (lane & 15);
    int aK   = (lane >> 4) * 16;                     // byte offset of k-half
    uint32_t aRowBase = baseA + aRow * 128;
    uint32_t aXor = (aRow & 7) << 4;

    int bRow = wn0 + (lane & 7) + ((lane >> 4) & 1) * 8;
    int bK   = ((lane >> 3) & 1) * 16;
    uint32_t bRowBase = baseB + bRow * 128;
    uint32_t bXor = (bRow & 7) << 4;

    // per-thread cp.async geometry: 2 threads per row, each covers 4x16B
    int ldRow = tid >> 1;                 // 0..127
    int ldCb  = (tid & 1) * 16;           // byte col of first 16B granule

    float acc[4][4][4];
    #pragma unroll
    for (int mt = 0; mt < 4; mt++)
        #pragma unroll
        for (int nt = 0; nt < 4; nt++)
            #pragma unroll
            for (int e = 0; e < 4; e++) acc[mt][nt][e] = 0.0f;

    int nch = K >> 6;                                // K-chunks of 64
    for (int ch = 0; ch < nch; ch++) {
        int k0 = ch << 6;
        // global -> smem via cp.async: FULL row coverage, 4 granules/thread/tile
        #pragma unroll
        for (int l = 0; l < 4; l++) {
            int cb = ldCb + l * 32;
            uint32_t off = swz(ldRow, cb);
            cp_async16(baseA + off, Ap + (long)ldRow * K + k0 + (cb >> 1));
            cp_async16(baseB + off, Bp + (long)ldRow * K + k0 + (cb >> 1));
        }
        CP_ASYNC_WAIT_ALL();
        __syncthreads();

        #pragma unroll
        for (int kk = 0; kk < 4; kk++) {             // 4 x k16 steps
            int kb = kk * 32;                        // byte offset of k16
            uint32_t aF[4][4], bF[2][4];
            #pragma unroll
            for (int mt = 0; mt < 4; mt++)
                ldsm_x4(aF[mt][0], aF[mt][1], aF[mt][2], aF[mt][3],
                        aRowBase + mt * (16 * 128) + ((kb + aK) ^ aXor));
            #pragma unroll
            for (int ntp = 0; ntp < 2; ntp++)
                ldsm_x4(bF[ntp][0], bF[ntp][1], bF[ntp][2], bF[ntp][3],
                        bRowBase + ntp * (16 * 128) + ((kb + bK) ^ bXor));
            #pragma unroll
            for (int mt = 0; mt < 4; mt++)
                #pragma unroll
                for (int nt = 0; nt < 4; nt++)
                    mma16816(acc[mt][nt], aF[mt], &bF[nt >> 1][(nt & 1) * 2]);
        }
        __syncthreads();
    }

    // ---------------- epilogue (fragment layout: c0,c1 row r, c2,c3 row r+8) --
    int rIn = lane >> 2;           // 0..7
    int cIn = (lane & 3) * 2;      // 0,2,4,6
    #pragma unroll
    for (int mt = 0; mt < 4; mt++) {
        long rowLo = m0 + wm0 + mt * 16 + rIn;
        long rowHi = rowLo + 8;
        #pragma unroll
        for (int nt = 0; nt < 4; nt++) {
            int col = wn0 + nt * 8 + cIn;            // 0..127 within tile
            float b0 = sBias[col], b1 = sBias[col + 1];
            float v0 = acc[mt][nt][0] + b0, v1 = acc[mt][nt][1] + b1;
            float v2 = acc[mt][nt][2] + b0, v3 = acc[mt][nt][3] + b1;
            if (mode == 0) {
                __nv_bfloat16* o = (__nv_bfloat16*)Cout + (long)t * strideCt;
                *(__nv_bfloat162*)(o + rowLo * Nfull + n0 + col) =
                    __floats2bfloat162_rn(fmaxf(v0, 0.f), fmaxf(v1, 0.f));
                *(__nv_bfloat162*)(o + rowHi * Nfull + n0 + col) =
                    __floats2bfloat162_rn(fmaxf(v2, 0.f), fmaxf(v3, 0.f));
            } else if (mode == 1) {
                __nv_bfloat16* o = (__nv_bfloat16*)Cout + (long)t * strideCt;
                *(__nv_bfloat162*)(o + rowLo * Nfull + n0 + col) =
                    __floats2bfloat162_rn(sigmoidf(v0), sigmoidf(v1));
                *(__nv_bfloat162*)(o + rowHi * Nfull + n0 + col) =
                    __floats2bfloat162_rn(sigmoidf(v2), sigmoidf(v3));
            } else {
                if (col < C_) {
                    float* o = (float*)Cout + (long)t * strideCt;
                    *(float2*)(o + rowLo * C_ + col) = make_float2(v0, v1);
                    *(float2*)(o + rowHi * C_ + col) = make_float2(v2, v3);
                }
            }
        }
    }
}

// ---------------------------------------------------------------------------
// elementwise fp32 -> bf16
// ---------------------------------------------------------------------------
__global__ __launch_bounds__(256) void conv_bf16(const float* __restrict__ in,
                                                 __nv_bfloat16* __restrict__ out,
                                                 int n)
{
    int i = blockIdx.x * 256 + threadIdx.x;
    if (i < n) out[i] = __float2bfloat16(in[i]);
}

// ---------------------------------------------------------------------------
// batched transpose + convert: in[t][R][Cc] f32  ->  out[t][Cc][R] bf16
// ---------------------------------------------------------------------------
__global__ __launch_bounds__(256) void transpose_bf16(const float* __restrict__ in,
                                                      __nv_bfloat16* __restrict__ out,
                                                      int R, int Cc)
{
    __shared__ float tile[32][33];
    int t = blockIdx.z;
    in  += (long)t * R * Cc;
    out += (long)t * R * Cc;
    int x = blockIdx.x * 32 + threadIdx.x;
    int y0 = blockIdx.y * 32;
    #pragma unroll
    for (int j = threadIdx.y; j < 32; j += 8)
        tile[j][threadIdx.x] = in[(long)(y0 + j) * Cc + x];
    __syncthreads();
    int xo = y0 + threadIdx.x;
    int yo0 = blockIdx.x * 32;
    #pragma unroll
    for (int j = threadIdx.y; j < 32; j += 8)
        out[(long)(yo0 + j) * R + xo] = __float2bfloat16(tile[threadIdx.x][j]);
}

// ---------------------------------------------------------------------------
// Routing product: 4 batch-rows per block (contiguous load), bf16 in/out.
// grid = (B_/4, T_), block = 512.
// ---------------------------------------------------------------------------
__global__ __launch_bounds__(512) void mu_kernel(const __nv_bfloat16* __restrict__ p,
                                                 __nv_bfloat16* __restrict__ mub)
{
    __shared__ float ps[4][L_];

    int b0 = blockIdx.x * 4;
    int t  = blockIdx.y;
    int tid = threadIdx.x;

    long base = ((long)t * B_ + b0) * L_;
    // 4 rows x 512 bf16 = 2048 contiguous bf16 = 1024 bf16x2
    const __nv_bfloat162* src = (const __nv_bfloat162*)(p + base);
    #pragma unroll
    for (int i = tid; i < 1024; i += 512) {
        __nv_bfloat162 v = src[i];
        int r = i >> 8;
        int c = (i & 255) * 2;
        ps[r][c]     = __bfloat162float(__low2bfloat16(v));
        ps[r][c + 1] = __bfloat162float(__high2bfloat16(v));
    }
    __syncthreads();

    int l = tid;
    #pragma unroll
    for (int r = 0; r < 4; r++) {
        float m = 1.0f;
        #pragma unroll
        for (int d = 0; d <= 8; d++) {
            int node = (1 << d) - 1 + (l >> (9 - d));
            float v = ps[r][node];
            m *= ((l >> (8 - d)) & 1) ? (1.0f - v) : v;
        }
        mub[base + (long)r * L_ + l] = __float2bfloat16(m);
    }
}

// ---------------------------------------------------------------------------
// softmax over classes with smem-staged transpose.
// grid = (L_/32, T_), block = 256 (8 warps x 4 rows). Coalesced 64B row writes.
// ---------------------------------------------------------------------------
__global__ __launch_bounds__(256) void softmaxT_kernel(const float* __restrict__ pi,
                                                       __nv_bfloat16* __restrict__ lpT)
{
    __shared__ __nv_bfloat16 tile[C_][34];

    int l0 = blockIdx.x * 32;
    int t  = blockIdx.y;
    int wid = threadIdx.x >> 5;
    int lane = threadIdx.x & 31;

    #pragma unroll
    for (int r = 0; r < 4; r++) {
        int lloc = wid * 4 + r;                        // 0..31
        const float* x = pi + ((long)t * L_ + l0 + lloc) * C_;

        float v[4];
        float mx = -1e30f;
        #pragma unroll
        for (int i = 0; i < 4; i++) {
            int c = lane + i * 32;
            v[i] = (c < C_) ? x[c] : -1e30f;
            mx = fmaxf(mx, v[i]);
        }
        #pragma unroll
        for (int o = 16; o > 0; o >>= 1)
            mx = fmaxf(mx, __shfl_xor_sync(0xffffffffu, mx, o));

        float s = 0.0f;
        #pragma unroll
        for (int i = 0; i < 4; i++) {
            int c = lane + i * 32;
            v[i] = (c < C_) ? expf(v[i] - mx) : 0.0f;
            s += v[i];
        }
        #pragma unroll
        for (int o = 16; o > 0; o >>= 1)
            s += __shfl_xor_sync(0xffffffffu, s, o);

        float inv = 1.0f / s;
        #pragma unroll
        for (int i = 0; i < 4; i++) {
            int c = lane + i * 32;
            if (c < C_) tile[c][lloc] = __float2bfloat16(v[i] * inv);
        }
    }
    __syncthreads();

    // coalesced write-out: rows of 32 contiguous bf16 (64B)
    __nv_bfloat16* o = lpT + (long)t * CP_ * L_ + l0;
    for (int idx = threadIdx.x; idx < C_ * 32; idx += 256) {
        int c = idx >> 5;
        int l = idx & 31;
        o[(long)c * L_ + l] = tile[c][l];
    }
}

// ---------------------------------------------------------------------------
// Deterministic reduce over trees + scale + log
// ---------------------------------------------------------------------------
__global__ __launch_bounds__(256) void finalize_kernel(const float* __restrict__ part,
                                                       float* __restrict__ out)
{
    int i = blockIdx.x * 256 + threadIdx.x;
    if (i >= B_ * C_) return;
    float s = 0.0f;
    #pragma unroll
    for (int t = 0; t < T_; t++) s += part[(long)t * B_ * C_ + i];
    out[i] = logf(s * (1.0f / (float)(L_ * T_)));
}

// ---------------------------------------------------------------------------
extern "C" void kernel_launch(void* const* d_in, const int* in_sizes, int n_in,
                              void* d_out, int out_size)
{
    const float* feat = (const float*)d_in[0];   // [B, F]
    const float* W1   = (const float*)d_in[1];   // [T, F, H]
    const float* b1   = (const float*)d_in[2];   // [T, H]
    const float* W2   = (const float*)d_in[3];   // [T, H, L]
    const float* b2   = (const float*)d_in[4];   // [T, L]
    const float* pi   = (const float*)d_in[5];   // [T, L, C]
    float* out        = (float*)d_out;           // [B, C]

    void *pfb, *pw1t, *pw2t, *phb, *ppb, *pmub, *plpT, *ppart;
    cudaGetSymbolAddress(&pfb,   g_featb);
    cudaGetSymbolAddress(&pw1t,  g_w1t);
    cudaGetSymbolAddress(&pw2t,  g_w2t);
    cudaGetSymbolAddress(&phb,   g_hb);
    cudaGetSymbolAddress(&ppb,   g_pb);
    cudaGetSymbolAddress(&pmub,  g_mub);
    cudaGetSymbolAddress(&plpT,  g_lpT);
    cudaGetSymbolAddress(&ppart, g_part);

    // operand prep
    conv_bf16<<<(B_ * F_ + 255) / 256, 256>>>(feat, (__nv_bfloat16*)pfb, B_ * F_);
    transpose_bf16<<<dim3(H_ / 32, F_ / 32, T_), dim3(32, 8)>>>(
        W1, (__nv_bfloat16*)pw1t, F_, H_);
    transpose_bf16<<<dim3(L_ / 32, H_ / 32, T_), dim3(32, 8)>>>(
        W2, (__nv_bfloat16*)pw2t, H_, L_);
    softmaxT_kernel<<<dim3(L_ / 32, T_), 256>>>(pi, (__nv_bfloat16*)plpT);

    // GEMM1: h = relu(feat @ W1 + b1)  M=1024 N=128 K=512
    gemm_tc<<<dim3(8, 1, T_), 256>>>(
        (const __nv_bfloat16*)pfb, 0L,
        (const __nv_bfloat16*)pw1t, (long)H_ * F_,
        b1, (long)H_,
        phb, (long)B_ * H_,
        F_, H_, /*mode=*/0);

    // GEMM2: p = sigmoid(h @ W2 + b2)  M=1024 N=512 K=128  (bf16 out)
    gemm_tc<<<dim3(8, 4, T_), 256>>>(
        (const __nv_bfloat16*)phb, (long)B_ * H_,
        (const __nv_bfloat16*)pw2t, (long)L_ * H_,
        b2, (long)L_,
        ppb, (long)B_ * L_,
        H_, L_, /*mode=*/1);

    // routing products (bf16 in, bf16 out)
    mu_kernel<<<dim3(B_ / 4, T_), 512>>>((const __nv_bfloat16*)ppb,
                                         (__nv_bfloat16*)pmub);

    // final contraction per tree: part[t] = mu[t] @ leafpT[t]^T
    gemm_tc<<<dim3(8, 1, T_), 256>>>(
        (const __nv_bfloat16*)pmub, (long)B_ * L_,
        (const __nv_bfloat16*)plpT, (long)CP_ * L_,
        b1 /*unused in mode 2*/, 0L,
        ppart, (long)B_ * C_,
        L_, 0, /*mode=*/2);

    // sum over trees, scale, log
    finalize_kernel<<<(B_ * C_ + 255) / 256, 256>>>((const float*)ppart, out);
}

// round 16
// speedup vs baseline: 1.3266x; 1.0273x over previous
#include <cuda_runtime.h>
#include <cuda_bf16.h>
#include <math.h>
#include <stdint.h>

#define T_ 16
#define B_ 1024
#define F_ 512
#define H_ 128
#define L_ 512
#define C_ 100
#define CP_ 128   // classes padded to 128 for the tensor GEMM

// ---------------- scratch (static device globals; zero-initialized) ---------
__device__ __nv_bfloat16 g_featb[B_ * F_];        // 1 MB
__device__ __nv_bfloat16 g_w1t[T_ * H_ * F_];     // 2 MB  (W1^T per tree: [H][F])
__device__ __nv_bfloat16 g_w2t[T_ * L_ * H_];     // 2 MB  (W2^T per tree: [L][H])
__device__ __nv_bfloat16 g_hb[T_ * B_ * H_];      // 4 MB
__device__ __nv_bfloat16 g_pb[T_ * B_ * L_];      // 16 MB (bf16 sigmoid output)
__device__ __nv_bfloat16 g_mub[T_ * B_ * L_];     // 16 MB
__device__ __nv_bfloat16 g_lpT[T_ * CP_ * L_];    // 2 MB (rows >= C_ stay 0 forever)
__device__ float         g_part[T_ * B_ * C_];    // 6.6 MB

__device__ __forceinline__ float sigmoidf(float x) {
    return 1.0f / (1.0f + __expf(-x));
}

__device__ __forceinline__ uint32_t smem_u32(const void* p) {
    uint32_t a;
    asm("{ .reg .u64 t; cvta.to.shared.u64 t, %1; cvt.u32.u64 %0, t; }"
        : "=r"(a) : "l"(p));
    return a;
}

// swizzled byte offset inside a [128 rows x 128 bytes] smem sub-tile
__device__ __forceinline__ uint32_t swz(int row, int colBytes) {
    return (uint32_t)(row * 128 + (colBytes ^ ((row & 7) << 4)));
}

__device__ __forceinline__ void cp_async16(uint32_t dst, const void* src) {
    asm volatile("cp.async.cg.shared.global [%0], [%1], 16;"
        :: "r"(dst), "l"(src) : "memory");
}
#define CP_ASYNC_WAIT_ALL() \
    asm volatile("cp.async.wait_all;" ::: "memory")

__device__ __forceinline__ void ldsm_x4(uint32_t& r0, uint32_t& r1,
                                        uint32_t& r2, uint32_t& r3, uint32_t addr) {
    asm volatile("ldmatrix.sync.aligned.m8n8.x4.shared.b16 {%0,%1,%2,%3}, [%4];"
        : "=r"(r0), "=r"(r1), "=r"(r2), "=r"(r3) : "r"(addr) : "memory");
}

__device__ __forceinline__ void mma16816(float* c, const uint32_t* a, const uint32_t* b) {
    asm volatile(
        "mma.sync.aligned.m16n8k16.row.col.f32.bf16.bf16.f32 "
        "{%0,%1,%2,%3}, {%4,%5,%6,%7}, {%8,%9}, {%0,%1,%2,%3};"
        : "+f"(c[0]), "+f"(c[1]), "+f"(c[2]), "+f"(c[3])
        : "r"(a[0]), "r"(a[1]), "r"(a[2]), "r"(a[3]), "r"(b[0]), "r"(b[1]));
}

// ===========================================================================
// HMMA batched GEMM — K-chunks of 128 (2 x 16KB sub-tiles/operand, one sync
// round per 128-K). Dynamic smem 64KB. Same MMA order as the 78us version.
// D[128 x 128] = A[128,K] @ Bw[128,K]^T  (bf16, f32 acc)
// A: [t][M][K] bf16 row-major.  Bw: [t][N][K] bf16 row-major (i.e. B^T).
// mode 0: out = bf16( relu(D + bias) )      (GEMM1 -> g_hb)
// mode 1: out = bf16( sigmoid(D + bias) )   (GEMM2 -> g_pb)
// mode 2: out = f32 ( D ), cols < C_ only   (final -> g_part, row stride C_)
// ===========================================================================
__global__ __launch_bounds__(256) void gemm_tc(
    const __nv_bfloat16* __restrict__ A, long strideAt,
    const __nv_bfloat16* __restrict__ Bw, long strideBt,
    const float* __restrict__ bias, long strideBiasT,
    void* __restrict__ Cout, long strideCt,
    int K, int Nfull, int mode)
{
    extern __shared__ __align__(128) uint8_t dynS[];
    // layout: A-sub0 @0, A-sub1 @16K, B-sub0 @32K, B-sub1 @48K
    __shared__ float sBias[128];

    int tid = threadIdx.x;
    int wid = tid >> 5;
    int lane = tid & 31;
    int t = blockIdx.z;
    int m0 = blockIdx.x * 128;
    int n0 = blockIdx.y * 128;

    const __nv_bfloat16* Ap = A + (long)t * strideAt + (long)m0 * K;
    const __nv_bfloat16* Bp = Bw + (long)t * strideBt + (long)n0 * K;

    if (tid < 128)
        sBias[tid] = (mode < 2) ? bias[(long)t * strideBiasT + n0 + tid] : 0.0f;

    int wm0 = (wid & 1) * 64;    // warp m-origin within tile
    int wn0 = (wid >> 1) * 32;   // warp n-origin within tile

    uint32_t base  = smem_u32(dynS);
    uint32_t baseA = base;            // 2 sub-tiles of 16KB
    uint32_t baseB = base + 32768;    // 2 sub-tiles of 16KB

    // ldmatrix lane geometry (byte offsets relative to a 16KB sub-tile)
    int aRow = wm0 + (lane & 15);
    int aK   = (lane >> 4) * 16;                     // byte offset of k-half
    uint32_t aRel = (uint32_t)aRow * 128;
    uint32_t aXor = (aRow & 7) << 4;

    int bRow = wn0 + (lane & 7) + ((lane >> 4) & 1) * 8;
    int bK   = ((lane >> 3) & 1) * 16;
    uint32_t bRel = (uint32_t)bRow * 128;
    uint32_t bXor = (bRow & 7) << 4;

    // per-thread cp.async geometry: 2 threads per row, each covers 4x16B/sub-tile
    int ldRow = tid >> 1;                 // 0..127
    int ldCb  = (tid & 1) * 16;           // byte col of first 16B granule

    float acc[4][4][4];
    #pragma unroll
    for (int mt = 0; mt < 4; mt++)
        #pragma unroll
        for (int nt = 0; nt < 4; nt++)
            #pragma unroll
            for (int e = 0; e < 4; e++) acc[mt][nt][e] = 0.0f;

    int nch = K >> 7;                                // K-chunks of 128
    for (int ch = 0; ch < nch; ch++) {
        int k0 = ch << 7;
        // fill both 64-K sub-tiles of A and B (full coverage)
        #pragma unroll
        for (int sc = 0; sc < 2; sc++) {
            int kk0 = k0 + sc * 64;
            uint32_t bA = baseA + sc * 16384;
            uint32_t bB = baseB + sc * 16384;
            #pragma unroll
            for (int l = 0; l < 4; l++) {
                int cb = ldCb + l * 32;
                uint32_t off = swz(ldRow, cb);
                cp_async16(bA + off, Ap + (long)ldRow * K + kk0 + (cb >> 1));
                cp_async16(bB + off, Bp + (long)ldRow * K + kk0 + (cb >> 1));
            }
        }
        CP_ASYNC_WAIT_ALL();
        __syncthreads();

        #pragma unroll
        for (int kk = 0; kk < 8; kk++) {             // 8 x k16 steps (2 sub-tiles)
            uint32_t bA = baseA + (kk >> 2) * 16384;
            uint32_t bB = baseB + (kk >> 2) * 16384;
            int kb = (kk & 3) * 32;                  // byte offset within sub-tile
            uint32_t aF[4][4], bF[2][4];
            #pragma unroll
            for (int mt = 0; mt < 4; mt++)
                ldsm_x4(aF[mt][0], aF[mt][1], aF[mt][2], aF[mt][3],
                        bA + aRel + mt * (16 * 128) + ((kb + aK) ^ aXor));
            #pragma unroll
            for (int ntp = 0; ntp < 2; ntp++)
                ldsm_x4(bF[ntp][0], bF[ntp][1], bF[ntp][2], bF[ntp][3],
                        bB + bRel + ntp * (16 * 128) + ((kb + bK) ^ bXor));
            #pragma unroll
            for (int mt = 0; mt < 4; mt++)
                #pragma unroll
                for (int nt = 0; nt < 4; nt++)
                    mma16816(acc[mt][nt], aF[mt], &bF[nt >> 1][(nt & 1) * 2]);
        }
        __syncthreads();
    }

    // ---------------- epilogue (fragment layout: c0,c1 row r, c2,c3 row r+8) --
    int rIn = lane >> 2;           // 0..7
    int cIn = (lane & 3) * 2;      // 0,2,4,6
    #pragma unroll
    for (int mt = 0; mt < 4; mt++) {
        long rowLo = m0 + wm0 + mt * 16 + rIn;
        long rowHi = rowLo + 8;
        #pragma unroll
        for (int nt = 0; nt < 4; nt++) {
            int col = wn0 + nt * 8 + cIn;            // 0..127 within tile
            float b0 = sBias[col], b1 = sBias[col + 1];
            float v0 = acc[mt][nt][0] + b0, v1 = acc[mt][nt][1] + b1;
            float v2 = acc[mt][nt][2] + b0, v3 = acc[mt][nt][3] + b1;
            if (mode == 0) {
                __nv_bfloat16* o = (__nv_bfloat16*)Cout + (long)t * strideCt;
                *(__nv_bfloat162*)(o + rowLo * Nfull + n0 + col) =
                    __floats2bfloat162_rn(fmaxf(v0, 0.f), fmaxf(v1, 0.f));
                *(__nv_bfloat162*)(o + rowHi * Nfull + n0 + col) =
                    __floats2bfloat162_rn(fmaxf(v2, 0.f), fmaxf(v3, 0.f));
            } else if (mode == 1) {
                __nv_bfloat16* o = (__nv_bfloat16*)Cout + (long)t * strideCt;
                *(__nv_bfloat162*)(o + rowLo * Nfull + n0 + col) =
                    __floats2bfloat162_rn(sigmoidf(v0), sigmoidf(v1));
                *(__nv_bfloat162*)(o + rowHi * Nfull + n0 + col) =
                    __floats2bfloat162_rn(sigmoidf(v2), sigmoidf(v3));
            } else {
                if (col < C_) {
                    float* o = (float*)Cout + (long)t * strideCt;
                    *(float2*)(o + rowLo * C_ + col) = make_float2(v0, v1);
                    *(float2*)(o + rowHi * C_ + col) = make_float2(v2, v3);
                }
            }
        }
    }
}

// ---------------------------------------------------------------------------
// elementwise fp32 -> bf16
// ---------------------------------------------------------------------------
__global__ __launch_bounds__(256) void conv_bf16(const float* __restrict__ in,
                                                 __nv_bfloat16* __restrict__ out,
                                                 int n)
{
    int i = blockIdx.x * 256 + threadIdx.x;
    if (i < n) out[i] = __float2bfloat16(in[i]);
}

// ---------------------------------------------------------------------------
// batched transpose + convert: in[t][R][Cc] f32  ->  out[t][Cc][R] bf16
// ---------------------------------------------------------------------------
__global__ __launch_bounds__(256) void transpose_bf16(const float* __restrict__ in,
                                                      __nv_bfloat16* __restrict__ out,
                                                      int R, int Cc)
{
    __shared__ float tile[32][33];
    int t = blockIdx.z;
    in  += (long)t * R * Cc;
    out += (long)t * R * Cc;
    int x = blockIdx.x * 32 + threadIdx.x;
    int y0 = blockIdx.y * 32;
    #pragma unroll
    for (int j = threadIdx.y; j < 32; j += 8)
        tile[j][threadIdx.x] = in[(long)(y0 + j) * Cc + x];
    __syncthreads();
    int xo = y0 + threadIdx.x;
    int yo0 = blockIdx.x * 32;
    #pragma unroll
    for (int j = threadIdx.y; j < 32; j += 8)
        out[(long)(yo0 + j) * R + xo] = __float2bfloat16(tile[threadIdx.x][j]);
}

// ---------------------------------------------------------------------------
// Routing product: 4 batch-rows per block (contiguous load), bf16 in/out.
// grid = (B_/4, T_), block = 512.
// ---------------------------------------------------------------------------
__global__ __launch_bounds__(512) void mu_kernel(const __nv_bfloat16* __restrict__ p,
                                                 __nv_bfloat16* __restrict__ mub)
{
    __shared__ float ps[4][L_];

    int b0 = blockIdx.x * 4;
    int t  = blockIdx.y;
    int tid = threadIdx.x;

    long base = ((long)t * B_ + b0) * L_;
    const __nv_bfloat162* src = (const __nv_bfloat162*)(p + base);
    #pragma unroll
    for (int i = tid; i < 1024; i += 512) {
        __nv_bfloat162 v = src[i];
        int r = i >> 8;
        int c = (i & 255) * 2;
        ps[r][c]     = __bfloat162float(__low2bfloat16(v));
        ps[r][c + 1] = __bfloat162float(__high2bfloat16(v));
    }
    __syncthreads();

    int l = tid;
    #pragma unroll
    for (int r = 0; r < 4; r++) {
        float m = 1.0f;
        #pragma unroll
        for (int d = 0; d <= 8; d++) {
            int node = (1 << d) - 1 + (l >> (9 - d));
            float v = ps[r][node];
            m *= ((l >> (8 - d)) & 1) ? (1.0f - v) : v;
        }
        mub[base + (long)r * L_ + l] = __float2bfloat16(m);
    }
}

// ---------------------------------------------------------------------------
// softmax over classes with smem-staged transpose.
// grid = (L_/32, T_), block = 256 (8 warps x 4 rows). Coalesced 64B row writes.
// ---------------------------------------------------------------------------
__global__ __launch_bounds__(256) void softmaxT_kernel(const float* __restrict__ pi,
                                                       __nv_bfloat16* __restrict__ lpT)
{
    __shared__ __nv_bfloat16 tile[C_][34];

    int l0 = blockIdx.x * 32;
    int t  = blockIdx.y;
    int wid = threadIdx.x >> 5;
    int lane = threadIdx.x & 31;

    #pragma unroll
    for (int r = 0; r < 4; r++) {
        int lloc = wid * 4 + r;                        // 0..31
        const float* x = pi + ((long)t * L_ + l0 + lloc) * C_;

        float v[4];
        float mx = -1e30f;
        #pragma unroll
        for (int i = 0; i < 4; i++) {
            int c = lane + i * 32;
            v[i] = (c < C_) ? x[c] : -1e30f;
            mx = fmaxf(mx, v[i]);
        }
        #pragma unroll
        for (int o = 16; o > 0; o >>= 1)
            mx = fmaxf(mx, __shfl_xor_sync(0xffffffffu, mx, o));

        float s = 0.0f;
        #pragma unroll
        for (int i = 0; i < 4; i++) {
            int c = lane + i * 32;
            v[i] = (c < C_) ? expf(v[i] - mx) : 0.0f;
            s += v[i];
        }
        #pragma unroll
        for (int o = 16; o > 0; o >>= 1)
            s += __shfl_xor_sync(0xffffffffu, s, o);

        float inv = 1.0f / s;
        #pragma unroll
        for (int i = 0; i < 4; i++) {
            int c = lane + i * 32;
            if (c < C_) tile[c][lloc] = __float2bfloat16(v[i] * inv);
        }
    }
    __syncthreads();

    // coalesced write-out: rows of 32 contiguous bf16 (64B)
    __nv_bfloat16* o = lpT + (long)t * CP_ * L_ + l0;
    for (int idx = threadIdx.x; idx < C_ * 32; idx += 256) {
        int c = idx >> 5;
        int l = idx & 31;
        o[(long)c * L_ + l] = tile[c][l];
    }
}

// ---------------------------------------------------------------------------
// Deterministic reduce over trees + scale + log
// ---------------------------------------------------------------------------
__global__ __launch_bounds__(256) void finalize_kernel(const float* __restrict__ part,
                                                       float* __restrict__ out)
{
    int i = blockIdx.x * 256 + threadIdx.x;
    if (i >= B_ * C_) return;
    float s = 0.0f;
    #pragma unroll
    for (int t = 0; t < T_; t++) s += part[(long)t * B_ * C_ + i];
    out[i] = logf(s * (1.0f / (float)(L_ * T_)));
}

// ---------------------------------------------------------------------------
extern "C" void kernel_launch(void* const* d_in, const int* in_sizes, int n_in,
                              void* d_out, int out_size)
{
    const float* feat = (const float*)d_in[0];   // [B, F]
    const float* W1   = (const float*)d_in[1];   // [T, F, H]
    const float* b1   = (const float*)d_in[2];   // [T, H]
    const float* W2   = (const float*)d_in[3];   // [T, H, L]
    const float* b2   = (const float*)d_in[4];   // [T, L]
    const float* pi   = (const float*)d_in[5];   // [T, L, C]
    float* out        = (float*)d_out;           // [B, C]

    void *pfb, *pw1t, *pw2t, *phb, *ppb, *pmub, *plpT, *ppart;
    cudaGetSymbolAddress(&pfb,   g_featb);
    cudaGetSymbolAddress(&pw1t,  g_w1t);
    cudaGetSymbolAddress(&pw2t,  g_w2t);
    cudaGetSymbolAddress(&phb,   g_hb);
    cudaGetSymbolAddress(&ppb,   g_pb);
    cudaGetSymbolAddress(&pmub,  g_mub);
    cudaGetSymbolAddress(&plpT,  g_lpT);
    cudaGetSymbolAddress(&ppart, g_part);

    // allow 64KB dynamic smem (unconditional — host-side, deterministic)
    cudaFuncSetAttribute(gemm_tc,
        cudaFuncAttributeMaxDynamicSharedMemorySize, 66560);
    const int GSM = 65536;

    // operand prep
    conv_bf16<<<(B_ * F_ + 255) / 256, 256>>>(feat, (__nv_bfloat16*)pfb, B_ * F_);
    transpose_bf16<<<dim3(H_ / 32, F_ / 32, T_), dim3(32, 8)>>>(
        W1, (__nv_bfloat16*)pw1t, F_, H_);
    transpose_bf16<<<dim3(L_ / 32, H_ / 32, T_), dim3(32, 8)>>>(
        W2, (__nv_bfloat16*)pw2t, H_, L_);
    softmaxT_kernel<<<dim3(L_ / 32, T_), 256>>>(pi, (__nv_bfloat16*)plpT);

    // GEMM1: h = relu(feat @ W1 + b1)  M=1024 N=128 K=512
    gemm_tc<<<dim3(8, 1, T_), 256, GSM>>>(
        (const __nv_bfloat16*)pfb, 0L,
        (const __nv_bfloat16*)pw1t, (long)H_ * F_,
        b1, (long)H_,
        phb, (long)B_ * H_,
        F_, H_, /*mode=*/0);

    // GEMM2: p = sigmoid(h @ W2 + b2)  M=1024 N=512 K=128  (bf16 out)
    gemm_tc<<<dim3(8, 4, T_), 256, GSM>>>(
        (const __nv_bfloat16*)phb, (long)B_ * H_,
        (const __nv_bfloat16*)pw2t, (long)L_ * H_,
        b2, (long)L_,
        ppb, (long)B_ * L_,
        H_, L_, /*mode=*/1);

    // routing products (bf16 in, bf16 out)
    mu_kernel<<<dim3(B_ / 4, T_), 512>>>((const __nv_bfloat16*)ppb,
                                         (__nv_bfloat16*)pmub);

    // final contraction per tree: part[t] = mu[t] @ leafpT[t]^T
    gemm_tc<<<dim3(8, 1, T_), 256, GSM>>>(
        (const __nv_bfloat16*)pmub, (long)B_ * L_,
        (const __nv_bfloat16*)plpT, (long)CP_ * L_,
        b1 /*unused in mode 2*/, 0L,
        ppart, (long)B_ * C_,
        L_, 0, /*mode=*/2);

    // sum over trees, scale, log
    finalize_kernel<<<(B_ * C_ + 255) / 256, 256>>>((const float*)ppart, out);
}